// round 12
// baseline (speedup 1.0000x reference)
#include <cuda_runtime.h>
#include <math.h>

#define N_   8
#define C_   64
#define H_   256
#define W_   256
#define K2_  9
#define NBLK 1024
#define QELEMS (H_ * W_ / 4)

// scratch (no cudaMalloc allowed); all counters monotonic => graph-replay safe
__device__ float g_part[N_ * C_ * 4];            // quarter-plane raw sums
__device__ unsigned int g_done[N_];              // pool completions per sample
__device__ unsigned int g_epoch_blk[NBLK];       // per-block replay counter

// ---------------------------------------------------------------------------
// Stencil for one 64-row x 256-col tile. Each warp: 4 tasks; a task is a
// 4-row x 128-col half-band. All 6 input rows preloaded (12+ independent LDG,
// MLP high) before SHFL/compute. Reflect padding resolved in-register.
// Tap weights read from smem inside the task loop (saves 9 live registers).
// ---------------------------------------------------------------------------
__device__ __forceinline__ void stencil_tile(
        const float* __restrict__ x, float* __restrict__ out,
        int plane, int tile, int warp, int lane,
        const float* wlfk, float A, float Bc, float lh1) {
    const size_t plane_off = (size_t)plane * (H_ * W_);
    const float* xp = x + plane_off;

    #pragma unroll 1
    for (int i = 0; i < 4; ++i) {
        const int T    = warp * 4 + i;      // 0..31
        const int band = T >> 1;            // 0..15 -> 4-row band
        const int half = T & 1;             // 128-col half
        const int y0   = tile * 64 + band * 4;
        const int cb   = half * 128 + lane * 4;

        float win[6][6];
        #pragma unroll
        for (int r = 0; r < 6; ++r) {
            int g = y0 - 1 + r;
            g = g < 0 ? 1 : (g >= H_ ? 2 * H_ - 2 - g : g);
            const float* rp = xp + (size_t)g * W_;
            float4 v = __ldg((const float4*)(rp + cb));
            float  e = __ldg(rp + (half ? 127 : 128));   // uniform boundary scalar
            float lf = __shfl_up_sync(0xffffffffu, v.w, 1);
            float rt = __shfl_down_sync(0xffffffffu, v.x, 1);
            if (half == 0) {
                if (lane == 0)  lf = v.y;   // reflect col -1 -> col 1
                if (lane == 31) rt = e;     // col 128 from other half
            } else {
                if (lane == 0)  lf = e;     // col 127 from other half
                if (lane == 31) rt = v.z;   // reflect col 256 -> col 254
            }
            win[r][0] = lf;
            win[r][1] = v.x; win[r][2] = v.y; win[r][3] = v.z; win[r][4] = v.w;
            win[r][5] = rt;
        }

        float* ob = out + plane_off + (size_t)y0 * W_ + cb;
        #pragma unroll
        for (int k = 0; k < 4; ++k) {
            float o[4];
            #pragma unroll
            for (int j = 0; j < 4; ++j) {
                float acc;
                acc = wlfk[0] * win[k][j];
                acc = fmaf(wlfk[1], win[k][j + 1], acc);
                acc = fmaf(wlfk[2], win[k][j + 2], acc);
                acc = fmaf(wlfk[3], win[k + 1][j],     acc);
                acc = fmaf(wlfk[4], win[k + 1][j + 1], acc);
                acc = fmaf(wlfk[5], win[k + 1][j + 2], acc);
                acc = fmaf(wlfk[6], win[k + 2][j],     acc);
                acc = fmaf(wlfk[7], win[k + 2][j + 1], acc);
                acc = fmaf(wlfk[8], win[k + 2][j + 2], acc);
                o[j] = fmaf(acc, A, fmaf(win[k + 1][j + 1], lh1, Bc));
            }
            __stcs((float4*)(ob + (size_t)k * W_),
                   make_float4(o[0], o[1], o[2], o[3]));
        }
    }
}

// ---------------------------------------------------------------------------
// Group-decoupled pipeline: 128-block group owns sample g. Each block pools
// 2 quarter-planes (k=0,1), group-local wait, then stencils 2 tiles in LIFO
// order (channel pooled in k=1 first). 1024 blocks / 5 blocks-per-SM for
// ~40 resident warps/SM (vs 27 in the 512-block version).
// ---------------------------------------------------------------------------
__global__ __launch_bounds__(256, 5) void fused_kernel(
        const float* __restrict__ x,
        const float* __restrict__ conv_w,
        const float* __restrict__ bn_gamma,
        const float* __restrict__ bn_beta,
        const float* __restrict__ bn_mean,
        const float* __restrict__ bn_var,
        const float* __restrict__ lamb_l,
        const float* __restrict__ lamb_h,
        const float* __restrict__ inside_all,
        float* __restrict__ out) {
    const int b    = blockIdx.x;
    const int g    = b >> 7;          // sample / group id
    const int r    = b & 127;         // rank within group
    const int tid  = threadIdx.x;
    const int warp = tid >> 5;
    const int lane = tid & 31;

    __shared__ float ws[8];
    __shared__ float ps[C_];
    __shared__ float wlf[2][K2_];
    __shared__ float cst[2][3];       // A, Bc, lh1 per stencil item

    unsigned int target = 0;
    if (tid == 0)
        target = (atomicAdd(&g_epoch_blk[b], 1u) + 1u) * 256u;

    // ---- pool: 2 quarter-plane items of sample g (k = 0,1) -----------------
    #pragma unroll 1
    for (int k = 0; k < 2; ++k) {
        const int item = g * 256 + r + 128 * k;
        const float4* xv = (const float4*)(x + (size_t)item * QELEMS);
        float s = 0.f;
        #pragma unroll
        for (int i = 0; i < 16; ++i) {
            float4 v = __ldg(&xv[tid + i * 256]);
            s += (v.x + v.y) + (v.z + v.w);
        }
        #pragma unroll
        for (int o = 16; o; o >>= 1) s += __shfl_down_sync(0xffffffffu, s, o);
        if (lane == 0) ws[warp] = s;
        __syncthreads();
        if (tid == 0)
            g_part[item] = ws[0] + ws[1] + ws[2] + ws[3]
                         + ws[4] + ws[5] + ws[6] + ws[7];
        __syncthreads();
    }

    // ---- group-local release + wait (128 blocks only) ----------------------
    if (tid == 0) {
        __threadfence();
        atomicAdd(&g_done[g], 2u);
        while (*((volatile unsigned int*)&g_done[g]) < target)
            __nanosleep(32);
    }
    __syncthreads();
    __threadfence();

    // ---- lf weights + constants for this block's 2 stencil channels --------
    // stencil item m: channel c_m, LIFO over pool halves:
    //   m=0 -> c = 32 + (r>>2)  (pooled in k=1, hottest)
    //   m=1 -> c = (r>>2)       (pooled in k=0)
    if (tid < C_) {
        const float* p = g_part + (g * C_ + tid) * 4;
        ps[tid] = (__ldcg(p) + __ldcg(p + 1) + __ldcg(p + 2) + __ldcg(p + 3))
                  * (1.f / (H_ * W_));
    }
    __syncthreads();
    if (tid < 18) {
        const int m  = tid / 9;
        const int t9 = tid - 9 * m;
        const int c  = (m == 0) ? (32 + (r >> 2)) : (r >> 2);
        const int jj = (c >> 3) * K2_ + t9;
        const float* wv = conv_w + jj * C_;
        float acc = 0.f;
        #pragma unroll
        for (int cc = 0; cc < C_; ++cc) acc = fmaf(ps[cc], wv[cc], acc);
        const float inv = rsqrtf(bn_var[jj] + 1e-5f);
        const float v = (acc - bn_mean[jj]) * (bn_gamma[jj] * inv) + bn_beta[jj];
        wlf[m][t9] = tanhf(v);
        if (t9 == 0) {
            const float ll  = __ldg(lamb_l + c);
            const float ia  = __ldg(inside_all + c);
            cst[m][0] = (ia + 1.f) * ll;          // A
            cst[m][1] = -ia * ps[c] * ll;         // Bc
            cst[m][2] = __ldg(lamb_h + c) + 1.f;  // lh1
        }
    }
    __syncthreads();

    // ---- 2 stencil tiles, LIFO over pooled halves ---------------------------
    const int tile = r & 3;
    #pragma unroll 1
    for (int m = 0; m < 2; ++m) {
        const int c     = (m == 0) ? (32 + (r >> 2)) : (r >> 2);
        const int plane = g * C_ + c;
        stencil_tile(x, out, plane, tile, warp, lane,
                     wlf[m], cst[m][0], cst[m][1], cst[m][2]);
    }
}

// ---------------------------------------------------------------------------
extern "C" void kernel_launch(void* const* d_in, const int* in_sizes, int n_in,
                              void* d_out, int out_size) {
    const float* x          = (const float*)d_in[0];
    const float* conv_w     = (const float*)d_in[1];
    const float* bn_gamma   = (const float*)d_in[2];
    const float* bn_beta    = (const float*)d_in[3];
    const float* bn_mean    = (const float*)d_in[4];
    const float* bn_var     = (const float*)d_in[5];
    const float* lamb_l     = (const float*)d_in[6];
    const float* lamb_h     = (const float*)d_in[7];
    const float* inside_all = (const float*)d_in[8];
    float* out = (float*)d_out;

    fused_kernel<<<NBLK, 256>>>(x, conv_w, bn_gamma, bn_beta, bn_mean, bn_var,
                                lamb_l, lamb_h, inside_all, out);
}

// round 13
// speedup vs baseline: 1.0881x; 1.0881x over previous
#include <cuda_runtime.h>
#include <math.h>

#define N_   8
#define C_   64
#define H_   256
#define W_   256
#define K2_  9
#define NBLK 512
#define QELEMS (H_ * W_ / 4)

// scratch (no cudaMalloc allowed); all counters monotonic => graph-replay safe
__device__ float g_part[N_ * C_ * 4];            // quarter-plane raw sums
__device__ unsigned int g_done[N_];              // pool completions per sample
__device__ unsigned int g_epoch_blk[NBLK];       // per-block replay counter

// ---------------------------------------------------------------------------
// Stencil for one 64-row x 256-col tile. Each warp: 4 tasks; a task is a
// 4-row x 128-col half-band. Load-all-then-accumulate: all 6 rows' loads
// (6 float4 + 6 edge scalars) are issued before ANY consumer, so the full
// MLP=12 is exposed; rows then stream into acc[4][4] and die.
// ---------------------------------------------------------------------------
__device__ __forceinline__ void stencil_tile(
        const float* __restrict__ x, float* __restrict__ out,
        int plane, int tile, int warp, int lane,
        const float* __restrict__ wlfk, float A, float Bc, float lh1) {
    const size_t plane_off = (size_t)plane * (H_ * W_);
    const float* xp = x + plane_off;

    const float w0 = wlfk[0], w1 = wlfk[1], w2 = wlfk[2];
    const float w3 = wlfk[3], w4 = wlfk[4], w5 = wlfk[5];
    const float w6 = wlfk[6], w7 = wlfk[7], w8 = wlfk[8];

    #pragma unroll 1
    for (int i = 0; i < 4; ++i) {
        const int T    = warp * 4 + i;      // 0..31
        const int band = T >> 1;            // 0..15 -> 4-row band
        const int half = T & 1;             // 128-col half
        const int y0   = tile * 64 + band * 4;
        const int cb   = half * 128 + lane * 4;
        const int ecol = half ? 127 : 128;  // cross-half boundary column

        // ---- phase 1: issue ALL loads (12 independent LDG) -----------------
        float4 v[6];
        float  e[6];
        #pragma unroll
        for (int r = 0; r < 6; ++r) {
            int g = y0 - 1 + r;
            g = g < 0 ? 1 : (g >= H_ ? 2 * H_ - 2 - g : g);
            const float* rp = xp + (size_t)g * W_;
            v[r] = __ldg((const float4*)(rp + cb));
            e[r] = __ldg(rp + ecol);
        }

        // ---- phase 2: stream rows into accumulators ------------------------
        float acc[4][4];
        #pragma unroll
        for (int k = 0; k < 4; ++k)
            #pragma unroll
            for (int j = 0; j < 4; ++j) acc[k][j] = 0.f;

        #pragma unroll
        for (int r = 0; r < 6; ++r) {
            float lf = __shfl_up_sync(0xffffffffu, v[r].w, 1);
            float rt = __shfl_down_sync(0xffffffffu, v[r].x, 1);
            if (half == 0) {
                if (lane == 0)  lf = v[r].y;   // reflect col -1 -> col 1
                if (lane == 31) rt = e[r];     // col 128 from other half
            } else {
                if (lane == 0)  lf = e[r];     // col 127 from other half
                if (lane == 31) rt = v[r].z;   // reflect col 256 -> col 254
            }
            float row[6];
            row[0] = lf;
            row[1] = v[r].x; row[2] = v[r].y; row[3] = v[r].z; row[4] = v[r].w;
            row[5] = rt;

            const int klo = (r - 2 < 0) ? 0 : r - 2;
            const int khi = (r < 3) ? r : 3;
            #pragma unroll
            for (int k = 0; k < 4; ++k) {
                if (k >= klo && k <= khi) {
                    const int wr = r - k;          // weight row 0..2
                    const float wa = (wr == 0) ? w0 : (wr == 1) ? w3 : w6;
                    const float wb = (wr == 0) ? w1 : (wr == 1) ? w4 : w7;
                    const float wc = (wr == 0) ? w2 : (wr == 1) ? w5 : w8;
                    #pragma unroll
                    for (int j = 0; j < 4; ++j) {
                        acc[k][j] = fmaf(wa, row[j],     acc[k][j]);
                        acc[k][j] = fmaf(wb, row[j + 1], acc[k][j]);
                        acc[k][j] = fmaf(wc, row[j + 2], acc[k][j]);
                    }
                }
            }
        }

        // ---- phase 3: epilogue (center term = v[k+1] components) -----------
        float* ob = out + plane_off + (size_t)y0 * W_ + cb;
        #pragma unroll
        for (int k = 0; k < 4; ++k) {
            const float4 ctr = v[k + 1];
            float4 o;
            o.x = fmaf(acc[k][0], A, fmaf(ctr.x, lh1, Bc));
            o.y = fmaf(acc[k][1], A, fmaf(ctr.y, lh1, Bc));
            o.z = fmaf(acc[k][2], A, fmaf(ctr.z, lh1, Bc));
            o.w = fmaf(acc[k][3], A, fmaf(ctr.w, lh1, Bc));
            __stcs((float4*)(ob + (size_t)k * W_), o);
        }
    }
}

// ---------------------------------------------------------------------------
// Group-decoupled pipeline: block group g (64 blocks, all co-resident) owns
// sample g. Pool quarters k=0..3, group-local wait, stencil LIFO k=3..0.
// ---------------------------------------------------------------------------
__global__ __launch_bounds__(256, 4) void fused_kernel(
        const float* __restrict__ x,
        const float* __restrict__ conv_w,
        const float* __restrict__ bn_gamma,
        const float* __restrict__ bn_beta,
        const float* __restrict__ bn_mean,
        const float* __restrict__ bn_var,
        const float* __restrict__ lamb_l,
        const float* __restrict__ lamb_h,
        const float* __restrict__ inside_all,
        float* __restrict__ out) {
    const int b    = blockIdx.x;
    const int g    = b >> 6;          // sample / group id
    const int r    = b & 63;          // rank within group
    const int tid  = threadIdx.x;
    const int warp = tid >> 5;
    const int lane = tid & 31;

    __shared__ float ws[8];
    __shared__ float ps[C_];
    __shared__ float wlf[4][K2_];
    __shared__ float cst[4][3];       // A, Bc, lh1 per k

    unsigned int target = 0;
    if (tid == 0)
        target = (atomicAdd(&g_epoch_blk[b], 1u) + 1u) * 256u;

    // ---- pool: 4 quarter-plane items of sample g (k = 0..3) ----------------
    #pragma unroll 1
    for (int k = 0; k < 4; ++k) {
        const int item = g * 256 + r + 64 * k;
        const float4* xv = (const float4*)(x + (size_t)item * QELEMS);
        float s = 0.f;
        #pragma unroll
        for (int i = 0; i < 16; ++i) {
            float4 v = __ldg(&xv[tid + i * 256]);
            s += (v.x + v.y) + (v.z + v.w);
        }
        #pragma unroll
        for (int o = 16; o; o >>= 1) s += __shfl_down_sync(0xffffffffu, s, o);
        if (lane == 0) ws[warp] = s;
        __syncthreads();
        if (tid == 0)
            g_part[item] = ws[0] + ws[1] + ws[2] + ws[3]
                         + ws[4] + ws[5] + ws[6] + ws[7];
        __syncthreads();
    }

    // ---- group-local release + wait (64 blocks only) -----------------------
    if (tid == 0) {
        __threadfence();
        atomicAdd(&g_done[g], 4u);
        while (*((volatile unsigned int*)&g_done[g]) < target)
            __nanosleep(32);
    }
    __syncthreads();
    __threadfence();

    // ---- lf weights + per-channel constants (all 4 k at once) --------------
    if (tid < C_) {
        const float* p = g_part + (g * C_ + tid) * 4;
        ps[tid] = (__ldcg(p) + __ldcg(p + 1) + __ldcg(p + 2) + __ldcg(p + 3))
                  * (1.f / (H_ * W_));
    }
    __syncthreads();
    if (tid < 36) {
        const int k  = tid / 9;
        const int t9 = tid - 9 * k;
        const int c  = (r >> 2) + 16 * k;
        const int jj = (c >> 3) * K2_ + t9;
        const float* wv = conv_w + jj * C_;
        float acc = 0.f;
        #pragma unroll
        for (int cc = 0; cc < C_; ++cc) acc = fmaf(ps[cc], wv[cc], acc);
        const float inv = rsqrtf(bn_var[jj] + 1e-5f);
        const float v = (acc - bn_mean[jj]) * (bn_gamma[jj] * inv) + bn_beta[jj];
        wlf[k][t9] = tanhf(v);
        if (t9 == 0) {
            const float ll  = __ldg(lamb_l + c);
            const float ia  = __ldg(inside_all + c);
            cst[k][0] = (ia + 1.f) * ll;          // A
            cst[k][1] = -ia * ps[c] * ll;         // Bc
            cst[k][2] = __ldg(lamb_h + c) + 1.f;  // lh1
        }
    }
    __syncthreads();

    // ---- 4 stencil tiles, LIFO over pooled quarters (k = 3..0) -------------
    const int tile = r & 3;
    #pragma unroll 1
    for (int k = 3; k >= 0; --k) {
        const int c     = (r >> 2) + 16 * k;
        const int plane = g * C_ + c;
        stencil_tile(x, out, plane, tile, warp, lane,
                     wlf[k], cst[k][0], cst[k][1], cst[k][2]);
    }
}

// ---------------------------------------------------------------------------
extern "C" void kernel_launch(void* const* d_in, const int* in_sizes, int n_in,
                              void* d_out, int out_size) {
    const float* x          = (const float*)d_in[0];
    const float* conv_w     = (const float*)d_in[1];
    const float* bn_gamma   = (const float*)d_in[2];
    const float* bn_beta    = (const float*)d_in[3];
    const float* bn_mean    = (const float*)d_in[4];
    const float* bn_var     = (const float*)d_in[5];
    const float* lamb_l     = (const float*)d_in[6];
    const float* lamb_h     = (const float*)d_in[7];
    const float* inside_all = (const float*)d_in[8];
    float* out = (float*)d_out;

    fused_kernel<<<NBLK, 256>>>(x, conv_w, bn_gamma, bn_beta, bn_mean, bn_var,
                                lamb_l, lamb_h, inside_all, out);
}